// round 1
// baseline (speedup 1.0000x reference)
#include <cuda_runtime.h>
#include <cstdint>

#define T_STEPS 512
#define BATCH   128
#define IN_DIM  512
#define HID     512
#define GCOLS   2048   // 4*HID, interleaved: j = 4*h + gate (0=f,1=i,2=g,3=o)
#define KDIM    512

// ---------------- static device scratch (no runtime allocation) ----------------
__device__ __align__(256) float g_Wx[KDIM * GCOLS];                       // [k][j] tf32-rounded
__device__ __align__(256) float g_Wh[HID * GCOLS];                        // [k][j] tf32-rounded
__device__ __align__(256) float g_bias[GCOLS];
__device__ __align__(256) float g_pre[(size_t)T_STEPS * BATCH * GCOLS];   // x-projection + bias
__device__ __align__(256) float g_hbuf[2][BATCH * HID];                   // double-buffered h
__device__ __align__(256) float g_cbuf[BATCH * HID];                      // c (owner-thread RMW)

// ---------------- helpers ----------------
__device__ __forceinline__ uint32_t f2tf(float f) {
    uint32_t u; asm("cvt.rna.tf32.f32 %0, %1;" : "=r"(u) : "f"(f)); return u;
}
__device__ __forceinline__ void cp16(void* s, const void* g) {
    uint32_t sa = (uint32_t)__cvta_generic_to_shared(s);
    asm volatile("cp.async.cg.shared.global [%0], [%1], 16;" :: "r"(sa), "l"(g));
}
__device__ __forceinline__ void cp_commit() { asm volatile("cp.async.commit_group;"); }
__device__ __forceinline__ void cp_wait1()  { asm volatile("cp.async.wait_group 1;"); }
__device__ __forceinline__ void cp_wait0()  { asm volatile("cp.async.wait_group 0;"); }

__device__ __forceinline__ void mma8(float* d, const uint32_t* a, uint32_t b0, uint32_t b1) {
    asm volatile(
        "mma.sync.aligned.m16n8k8.row.col.f32.tf32.tf32.f32 "
        "{%0,%1,%2,%3}, {%4,%5,%6,%7}, {%8,%9}, {%0,%1,%2,%3};"
        : "+f"(d[0]), "+f"(d[1]), "+f"(d[2]), "+f"(d[3])
        : "r"(a[0]), "r"(a[1]), "r"(a[2]), "r"(a[3]), "r"(b0), "r"(b1));
}
__device__ __forceinline__ float sigf(float x) { return 1.0f / (1.0f + __expf(-x)); }

// ---------------- weight packing: W[h][1024] -> Wx[k][4h+g], Wh[k][4h+g] ----------------
__global__ void pack_kernel(const float* __restrict__ Wf, const float* __restrict__ bf,
                            const float* __restrict__ Wi, const float* __restrict__ bi,
                            const float* __restrict__ Wg, const float* __restrict__ bg,
                            const float* __restrict__ Wo, const float* __restrict__ bo) {
    int j = blockIdx.x;            // 0..2047
    int h = j >> 2, gi = j & 3;
    const float* W; const float* bb;
    if (gi == 0)      { W = Wf; bb = bf; }
    else if (gi == 1) { W = Wi; bb = bi; }
    else if (gi == 2) { W = Wg; bb = bg; }
    else              { W = Wo; bb = bo; }
    int k = threadIdx.x;           // 0..511
    g_Wx[k * GCOLS + j] = __uint_as_float(f2tf(W[h * 1024 + k]));
    g_Wh[k * GCOLS + j] = __uint_as_float(f2tf(W[h * 1024 + 512 + k]));
    if (k == 0) g_bias[j] = bb[h];
}

__global__ void init_state() {
    int i = blockIdx.x * blockDim.x + threadIdx.x;
    if (i < BATCH * HID) { g_hbuf[0][i] = 0.0f; g_cbuf[i] = 0.0f; }
}

// ---------------- precompute GEMM: pre = X @ WxT + bias ----------------
// A = X [65536 x 512] row-major, B = g_Wx [512 x 2048] k-major.
// BM=64 BN=64 BK=32, 256 threads, warps 2(M) x 4(N), warp tile 32x16.
__global__ __launch_bounds__(256) void gemm_pre(const float* __restrict__ X) {
    __shared__ __align__(128) float As[2][64 * 36];
    __shared__ __align__(128) float Bs[2][32 * 68];
    const int tid = threadIdx.x;
    const int m0 = blockIdx.x * 64, n0 = blockIdx.y * 64;
    const int warp = tid >> 5, lane = tid & 31;
    const int wm = warp >> 2, wn = warp & 3;
    const int gid = lane >> 2, tig = lane & 3;

    float acc[2][2][4];
    #pragma unroll
    for (int i0 = 0; i0 < 2; i0++)
        #pragma unroll
        for (int i1 = 0; i1 < 2; i1++)
            #pragma unroll
            for (int i2 = 0; i2 < 4; i2++) acc[i0][i1][i2] = 0.0f;

    auto load_tiles = [&](int buf, int k0) {
        #pragma unroll
        for (int i = 0; i < 2; i++) {
            int c = tid * 2 + i;                 // 512 chunks: 64 rows x 8
            int row = c >> 3, cw = c & 7;
            cp16(&As[buf][row * 36 + cw * 4], X + (size_t)(m0 + row) * 512 + k0 + cw * 4);
        }
        #pragma unroll
        for (int i = 0; i < 2; i++) {
            int c = tid * 2 + i;                 // 512 chunks: 32 rows x 16
            int row = c >> 4, cw = c & 15;
            cp16(&Bs[buf][row * 68 + cw * 4], g_Wx + (size_t)(k0 + row) * GCOLS + n0 + cw * 4);
        }
        cp_commit();
    };

    load_tiles(0, 0);
    for (int kt = 0; kt < 16; kt++) {
        if (kt < 15) { load_tiles((kt + 1) & 1, (kt + 1) * 32); cp_wait1(); }
        else cp_wait0();
        __syncthreads();
        const float* A_ = As[kt & 1];
        const float* B_ = Bs[kt & 1];
        #pragma unroll
        for (int ks = 0; ks < 4; ks++) {
            const int kb = ks * 8;
            uint32_t a[2][4];
            #pragma unroll
            for (int mf = 0; mf < 2; mf++) {
                int r = wm * 32 + mf * 16;
                a[mf][0] = __float_as_uint(A_[(r + gid) * 36 + kb + tig]);
                a[mf][1] = __float_as_uint(A_[(r + gid + 8) * 36 + kb + tig]);
                a[mf][2] = __float_as_uint(A_[(r + gid) * 36 + kb + tig + 4]);
                a[mf][3] = __float_as_uint(A_[(r + gid + 8) * 36 + kb + tig + 4]);
            }
            #pragma unroll
            for (int nf = 0; nf < 2; nf++) {
                int cc = wn * 16 + nf * 8 + gid;
                uint32_t b0 = __float_as_uint(B_[(kb + tig) * 68 + cc]);
                uint32_t b1 = __float_as_uint(B_[(kb + tig + 4) * 68 + cc]);
                mma8(acc[0][nf], a[0], b0, b1);
                mma8(acc[1][nf], a[1], b0, b1);
            }
        }
        __syncthreads();
    }

    #pragma unroll
    for (int mf = 0; mf < 2; mf++)
        #pragma unroll
        for (int nf = 0; nf < 2; nf++) {
            int row0 = m0 + wm * 32 + mf * 16 + gid;
            int col  = n0 + wn * 16 + nf * 8 + tig * 2;
            float bb0 = g_bias[col], bb1 = g_bias[col + 1];
            float2 s0 = make_float2(acc[mf][nf][0] + bb0, acc[mf][nf][1] + bb1);
            float2 s1 = make_float2(acc[mf][nf][2] + bb0, acc[mf][nf][3] + bb1);
            *(float2*)&g_pre[(size_t)row0 * GCOLS + col]       = s0;
            *(float2*)&g_pre[(size_t)(row0 + 8) * GCOLS + col] = s1;
        }
}

// ---------------- recurrent step: gates = pre[t] + h_{t-1} @ WhT, fused LSTM epilogue ----------------
// BM=32 BN=64 BK=32, 256 threads, warps 2(M) x 4(N), warp tile 16x16. Grid 4 x 32 = 128 blocks.
__global__ __launch_bounds__(256) void lstm_step(int t, float* __restrict__ out) {
    __shared__ __align__(128) float As[2][32 * 36];
    __shared__ __align__(128) float Bs[2][32 * 68];
    const int tid = threadIdx.x;
    const int b0_ = blockIdx.x * 32, n0 = blockIdx.y * 64;
    const int warp = tid >> 5, lane = tid & 31;
    const int wm = warp >> 2, wn = warp & 3;
    const int gid = lane >> 2, tig = lane & 3;
    const int rbuf = t & 1, wbuf = rbuf ^ 1;
    const float* __restrict__ H = g_hbuf[rbuf];

    float acc[2][4];
    #pragma unroll
    for (int i0 = 0; i0 < 2; i0++)
        #pragma unroll
        for (int i1 = 0; i1 < 4; i1++) acc[i0][i1] = 0.0f;

    auto load_tiles = [&](int buf, int k0) {
        {
            int row = tid >> 3, cw = tid & 7;    // 256 chunks: 32 rows x 8
            cp16(&As[buf][row * 36 + cw * 4], H + (size_t)(b0_ + row) * 512 + k0 + cw * 4);
        }
        #pragma unroll
        for (int i = 0; i < 2; i++) {
            int c = tid * 2 + i;                 // 512 chunks: 32 rows x 16
            int row = c >> 4, cw = c & 15;
            cp16(&Bs[buf][row * 68 + cw * 4], g_Wh + (size_t)(k0 + row) * GCOLS + n0 + cw * 4);
        }
        cp_commit();
    };

    load_tiles(0, 0);
    for (int kt = 0; kt < 16; kt++) {
        if (kt < 15) { load_tiles((kt + 1) & 1, (kt + 1) * 32); cp_wait1(); }
        else cp_wait0();
        __syncthreads();
        const float* A_ = As[kt & 1];
        const float* B_ = Bs[kt & 1];
        #pragma unroll
        for (int ks = 0; ks < 4; ks++) {
            const int kb = ks * 8;
            const int r = wm * 16;
            uint32_t a[4];
            a[0] = __float_as_uint(A_[(r + gid) * 36 + kb + tig]);
            a[1] = __float_as_uint(A_[(r + gid + 8) * 36 + kb + tig]);
            a[2] = __float_as_uint(A_[(r + gid) * 36 + kb + tig + 4]);
            a[3] = __float_as_uint(A_[(r + gid + 8) * 36 + kb + tig + 4]);
            #pragma unroll
            for (int nf = 0; nf < 2; nf++) {
                int cc = wn * 16 + nf * 8 + gid;
                uint32_t b0 = __float_as_uint(B_[(kb + tig) * 68 + cc]);
                uint32_t b1 = __float_as_uint(B_[(kb + tig + 4) * 68 + cc]);
                mma8(acc[nf], a, b0, b1);
            }
        }
        __syncthreads();
    }

    // Fused LSTM epilogue. j = 4*h + gate; lane pair (tig, tig^1) holds the 4 gates of one h.
    const float* __restrict__ pr = g_pre + (size_t)t * BATCH * GCOLS;
    #pragma unroll
    for (int nf = 0; nf < 2; nf++) {
        int row0 = b0_ + wm * 16 + gid;
        int col  = n0 + wn * 16 + nf * 8 + tig * 2;
        float2 p0 = *(const float2*)&pr[(size_t)row0 * GCOLS + col];
        float2 p1 = *(const float2*)&pr[(size_t)(row0 + 8) * GCOLS + col];
        float v0 = acc[nf][0] + p0.x, v1 = acc[nf][1] + p0.y;
        float v2 = acc[nf][2] + p1.x, v3 = acc[nf][3] + p1.y;
        float u0 = __shfl_xor_sync(0xffffffffu, v0, 1);
        float u1 = __shfl_xor_sync(0xffffffffu, v1, 1);
        float u2 = __shfl_xor_sync(0xffffffffu, v2, 1);
        float u3 = __shfl_xor_sync(0xffffffffu, v3, 1);
        if ((tig & 1) == 0) {
            int h = col >> 2;   // col = 4*h (even tig) -> own cols are f,i; partner has g,o
            {
                float f = sigf(v0), ii = sigf(v1), g = tanhf(u0), o = sigf(u1);
                int idx = row0 * HID + h;
                float c = f * g_cbuf[idx] + ii * g;
                g_cbuf[idx] = c;
                float hn = o * tanhf(c);
                g_hbuf[wbuf][idx] = hn;
                out[(size_t)t * (BATCH * HID) + idx] = hn;
            }
            {
                float f = sigf(v2), ii = sigf(v3), g = tanhf(u2), o = sigf(u3);
                int idx = (row0 + 8) * HID + h;
                float c = f * g_cbuf[idx] + ii * g;
                g_cbuf[idx] = c;
                float hn = o * tanhf(c);
                g_hbuf[wbuf][idx] = hn;
                out[(size_t)t * (BATCH * HID) + idx] = hn;
            }
        }
    }
}

// ---------------- final (hx, cx) tail ----------------
__global__ void finalize(float* __restrict__ out) {
    int i = blockIdx.x * blockDim.x + threadIdx.x;
    if (i < BATCH * HID) {
        // T_STEPS is even: last step (t=511) wrote h into buffer 0
        out[(size_t)T_STEPS * BATCH * HID + i]               = g_hbuf[0][i];
        out[(size_t)T_STEPS * BATCH * HID + BATCH * HID + i] = g_cbuf[i];
    }
}

// ---------------- launch ----------------
extern "C" void kernel_launch(void* const* d_in, const int* in_sizes, int n_in,
                              void* d_out, int out_size) {
    const float* X  = (const float*)d_in[0];
    const float* Wf = (const float*)d_in[1];
    const float* bf = (const float*)d_in[2];
    const float* Wi = (const float*)d_in[3];
    const float* bi = (const float*)d_in[4];
    const float* Wg = (const float*)d_in[5];
    const float* bg = (const float*)d_in[6];
    const float* Wo = (const float*)d_in[7];
    const float* bo = (const float*)d_in[8];
    float* out = (float*)d_out;

    pack_kernel<<<GCOLS, 512>>>(Wf, bf, Wi, bi, Wg, bg, Wo, bo);
    init_state<<<(BATCH * HID + 255) / 256, 256>>>();
    gemm_pre<<<dim3(65536 / 64, GCOLS / 64), 256>>>(X);
    for (int t = 0; t < T_STEPS; t++)
        lstm_step<<<dim3(BATCH / 32, GCOLS / 64), 256>>>(t, out);
    finalize<<<(BATCH * HID + 255) / 256, 256>>>(out);
}

// round 3
// speedup vs baseline: 1.9469x; 1.9469x over previous
#include <cuda_runtime.h>
#include <cstdint>

#define T_STEPS 512
#define BATCH   128
#define HID     512
#define GCOLS   2048   // 4*HID, interleaved: j = 4*h + gate (0=f,1=i,2=g,3=o)
#define KDIM    512

// ---------------- static device scratch ----------------
__device__ __align__(256) float g_Wx[KDIM * GCOLS];                       // [k][j] tf32 (for pre-GEMM)
__device__ __align__(256) float g_WhF[HID * GCOLS];                       // frag-packed Wh (4MB)
__device__ __align__(256) float g_bias[GCOLS];
__device__ __align__(256) float g_pre[(size_t)T_STEPS * BATCH * GCOLS];   // x-proj + bias (512MB)
__device__ __align__(256) float g_hF[2][BATCH * HID];                     // h, fragment layout, dbl-buffered
__device__ unsigned int g_bar[4];                                         // per-batch-group barrier

// ---------------- helpers ----------------
__device__ __forceinline__ uint32_t f2tf(float f) {
    uint32_t u; asm("cvt.rna.tf32.f32 %0, %1;" : "=r"(u) : "f"(f)); return u;
}
__device__ __forceinline__ void cp16(void* s, const void* g) {
    uint32_t sa = (uint32_t)__cvta_generic_to_shared(s);
    asm volatile("cp.async.cg.shared.global [%0], [%1], 16;" :: "r"(sa), "l"(g));
}
__device__ __forceinline__ void cp_commit() { asm volatile("cp.async.commit_group;"); }
__device__ __forceinline__ void cp_wait0()  { asm volatile("cp.async.wait_group 0;"); }
__device__ __forceinline__ void cp_wait1()  { asm volatile("cp.async.wait_group 1;"); }

__device__ __forceinline__ void mma8(float* d, const uint32_t* a, uint32_t b0, uint32_t b1) {
    asm volatile(
        "mma.sync.aligned.m16n8k8.row.col.f32.tf32.tf32.f32 "
        "{%0,%1,%2,%3}, {%4,%5,%6,%7}, {%8,%9}, {%0,%1,%2,%3};"
        : "+f"(d[0]), "+f"(d[1]), "+f"(d[2]), "+f"(d[3])
        : "r"(a[0]), "r"(a[1]), "r"(a[2]), "r"(a[3]), "r"(b0), "r"(b1));
}
__device__ __forceinline__ float sigf(float x) { return 1.0f / (1.0f + __expf(-x)); }

// ---------------- pack: Wx (k-major, for pre-GEMM) + bias ----------------
__global__ void pack_wx(const float* __restrict__ Wf, const float* __restrict__ bf,
                        const float* __restrict__ Wi, const float* __restrict__ bi,
                        const float* __restrict__ Wg, const float* __restrict__ bg,
                        const float* __restrict__ Wo, const float* __restrict__ bo) {
    int j = blockIdx.x;            // 0..2047
    int h = j >> 2, gi = j & 3;
    const float* W; const float* bb;
    if (gi == 0)      { W = Wf; bb = bf; }
    else if (gi == 1) { W = Wi; bb = bi; }
    else if (gi == 2) { W = Wg; bb = bg; }
    else              { W = Wo; bb = bo; }
    int k = threadIdx.x;           // 0..511
    g_Wx[k * GCOLS + j] = __uint_as_float(f2tf(W[h * 1024 + k]));
    if (k == 0) g_bias[j] = bb[h];
}

// ---------------- pack: Wh fragment layout ----------------
// g_WhF flat index: ((((nb*4 + ws)*16 + ksl)*2 + wq)*2 + pair)*32*4 + lane*4 + slot
// slot: {nf=pair*2 + slot>>1, b01 = slot&1}; k = ws*128 + ksl*8 + b01*4 + tig
// col = nb*64 + wq*32 + nf*8 + gid
__global__ void pack_whf(const float* __restrict__ Wf, const float* __restrict__ Wi,
                         const float* __restrict__ Wg, const float* __restrict__ Wo) {
    unsigned f = blockIdx.x * 256u + threadIdx.x;   // 0 .. 2^20-1
    int slot = f & 3;
    int lane = (f >> 2) & 31;
    int pair = (f >> 7) & 1;
    int wq   = (f >> 8) & 1;
    int ksl  = (f >> 9) & 15;
    int ws   = (f >> 13) & 3;
    int nb   = f >> 15;
    int gid = lane >> 2, tig = lane & 3;
    int nf  = pair * 2 + (slot >> 1);
    int b01 = slot & 1;
    int k   = ws * 128 + ksl * 8 + b01 * 4 + tig;
    int col = nb * 64 + wq * 32 + nf * 8 + gid;
    int h = col >> 2, gate = col & 3;
    const float* W;
    if (gate == 0) W = Wf; else if (gate == 1) W = Wi;
    else if (gate == 2) W = Wg; else W = Wo;
    g_WhF[f] = __uint_as_float(f2tf(W[h * 1024 + 512 + k]));
}

__global__ void init_state() {
    int i = blockIdx.x * blockDim.x + threadIdx.x;
    if (i < 4) g_bar[i] = 0;
    if (i < 2 * BATCH * HID) ((float*)g_hF)[i] = 0.0f;
}

// ---------------- precompute GEMM: pre = X @ WxT + bias ----------------
__global__ __launch_bounds__(256) void gemm_pre(const float* __restrict__ X) {
    __shared__ __align__(128) float As[2][64 * 36];
    __shared__ __align__(128) float Bs[2][32 * 68];
    const int tid = threadIdx.x;
    const int m0 = blockIdx.x * 64, n0 = blockIdx.y * 64;
    const int warp = tid >> 5, lane = tid & 31;
    const int wm = warp >> 2, wn = warp & 3;
    const int gid = lane >> 2, tig = lane & 3;

    float acc[2][2][4];
    #pragma unroll
    for (int i0 = 0; i0 < 2; i0++)
        #pragma unroll
        for (int i1 = 0; i1 < 2; i1++)
            #pragma unroll
            for (int i2 = 0; i2 < 4; i2++) acc[i0][i1][i2] = 0.0f;

    auto load_tiles = [&](int buf, int k0) {
        #pragma unroll
        for (int i = 0; i < 2; i++) {
            int c = tid * 2 + i;
            int row = c >> 3, cw = c & 7;
            cp16(&As[buf][row * 36 + cw * 4], X + (size_t)(m0 + row) * 512 + k0 + cw * 4);
        }
        #pragma unroll
        for (int i = 0; i < 2; i++) {
            int c = tid * 2 + i;
            int row = c >> 4, cw = c & 15;
            cp16(&Bs[buf][row * 68 + cw * 4], g_Wx + (size_t)(k0 + row) * GCOLS + n0 + cw * 4);
        }
        cp_commit();
    };

    load_tiles(0, 0);
    for (int kt = 0; kt < 16; kt++) {
        if (kt < 15) { load_tiles((kt + 1) & 1, (kt + 1) * 32); cp_wait1(); }
        else cp_wait0();
        __syncthreads();
        const float* A_ = As[kt & 1];
        const float* B_ = Bs[kt & 1];
        #pragma unroll
        for (int ks = 0; ks < 4; ks++) {
            const int kb = ks * 8;
            uint32_t a[2][4];
            #pragma unroll
            for (int mf = 0; mf < 2; mf++) {
                int r = wm * 32 + mf * 16;
                a[mf][0] = __float_as_uint(A_[(r + gid) * 36 + kb + tig]);
                a[mf][1] = __float_as_uint(A_[(r + gid + 8) * 36 + kb + tig]);
                a[mf][2] = __float_as_uint(A_[(r + gid) * 36 + kb + tig + 4]);
                a[mf][3] = __float_as_uint(A_[(r + gid + 8) * 36 + kb + tig + 4]);
            }
            #pragma unroll
            for (int nf = 0; nf < 2; nf++) {
                int cc = wn * 16 + nf * 8 + gid;
                uint32_t b0 = __float_as_uint(B_[(kb + tig) * 68 + cc]);
                uint32_t b1 = __float_as_uint(B_[(kb + tig + 4) * 68 + cc]);
                mma8(acc[0][nf], a[0], b0, b1);
                mma8(acc[1][nf], a[1], b0, b1);
            }
        }
        __syncthreads();
    }

    #pragma unroll
    for (int mf = 0; mf < 2; mf++)
        #pragma unroll
        for (int nf = 0; nf < 2; nf++) {
            int row0 = m0 + wm * 32 + mf * 16 + gid;
            int col  = n0 + wn * 16 + nf * 8 + tig * 2;
            float bb0 = g_bias[col], bb1 = g_bias[col + 1];
            float2 s0 = make_float2(acc[mf][nf][0] + bb0, acc[mf][nf][1] + bb1);
            float2 s1 = make_float2(acc[mf][nf][2] + bb0, acc[mf][nf][3] + bb1);
            *(float2*)&g_pre[(size_t)row0 * GCOLS + col]       = s0;
            *(float2*)&g_pre[(size_t)(row0 + 8) * GCOLS + col] = s1;
        }
}

// ---------------- persistent recurrent kernel ----------------
// Grid: 128 blocks = 4 batch-groups x 32 n-slices. 256 threads (8 warps).
// Block tile: 32 batch rows x 64 gate cols, K=512 split 4-way across warps (S=4),
// 2 warps per n-half (Q=2). Wh slice resident in smem (128KB frag-packed).
__global__ __launch_bounds__(256) void lstm_persist(float* __restrict__ out) {
    extern __shared__ float smem[];
    float* WhS = smem;               // 32768 floats (128KB)
    float* As  = smem + 32768;       // 16384 floats (h stage, frag layout)
    float* redbuf  = As;             // 6144 floats [wq][src3][grp8][lane][4]
    float* gatebuf = As + 6144;      // 32*68 floats

    const int tid  = threadIdx.x;
    const int lane = tid & 31;
    const int w    = tid >> 5;
    const int ws   = w >> 1;         // k-slice 0..3
    const int wq   = w & 1;          // n-half 0..1
    const int gid  = lane >> 2, tig = lane & 3;

    const int bg  = blockIdx.x >> 5;       // batch group 0..3
    const int nb  = blockIdx.x & 31;       // n-slice 0..31
    const int b0_ = bg * 32;
    const int n0  = nb * 64;
    const int mg0 = bg * 2;

    // --- load full Wh slice into smem: 32768 floats = 32 iters x 256 thr x 16B ---
    {
        const float* src = g_WhF + (size_t)nb * 32768;
        #pragma unroll
        for (int i = 0; i < 32; i++) {
            int c = tid + i * 256;
            cp16(&WhS[c * 4], src + (size_t)c * 4);
        }
        cp_commit(); cp_wait0();
        __syncthreads();
    }

    // epilogue cell mapping (fixed for all steps)
    const int b_loc = tid >> 3;            // 0..31
    const int hloc0 = (tid & 7) * 2;       // 0..14
    const int bglob = b0_ + b_loc;
    const int hg    = nb * 16 + hloc0;     // global h index of cell0
    // h fragment-layout offset for (bglob, k=hg)
    const int mg_e = bglob >> 4, rr = bglob & 15, up = rr >> 3, gb = rr & 7;
    const int wsk = hg >> 7, kslk = (hg >> 3) & 15, tigk = hg & 3, hik = (hg >> 2) & 1;
    const int hoff = (((mg_e * 4 + wsk) * 16 + kslk) * 32 + (gb * 4 + tigk)) * 4 + (up + 2 * hik);

    float c0 = 0.0f, c1 = 0.0f;

    for (int t = 0; t < T_STEPS; t++) {
        const int rb = t & 1, wb = rb ^ 1;

        // --- stage h[rb] (64KB contiguous, frag layout) ---
        const float* src = g_hF[rb] + mg0 * 8192;
        #pragma unroll
        for (int i = 0; i < 16; i++) {
            int c = tid + i * 256;
            cp16(&As[c * 4], src + c * 4);
        }
        cp_commit();

        // prefetch pre[t] for this thread's cells (hidden behind stage wait)
        const float* prp = g_pre + (size_t)t * (BATCH * GCOLS)
                         + (size_t)bglob * GCOLS + n0 + hloc0 * 4;
        float4 pA = *(const float4*)prp;
        float4 pB = *(const float4*)(prp + 4);

        cp_wait0();
        __syncthreads();

        // --- mainloop: warp (ws,wq) computes 32x32 over k in [ws*128, ws*128+128) ---
        float acc[2][4][4];
        #pragma unroll
        for (int i0 = 0; i0 < 2; i0++)
            #pragma unroll
            for (int i1 = 0; i1 < 4; i1++)
                #pragma unroll
                for (int i2 = 0; i2 < 4; i2++) acc[i0][i1][i2] = 0.0f;

        #pragma unroll
        for (int ksl = 0; ksl < 16; ksl++) {
            uint4 a0v = *(const uint4*)&As[(((0 * 4 + ws) * 16 + ksl) * 32 + lane) * 4];
            uint4 a1v = *(const uint4*)&As[(((1 * 4 + ws) * 16 + ksl) * 32 + lane) * 4];
            uint4 b0v = *(const uint4*)&WhS[((((ws * 16 + ksl) * 2 + wq) * 2 + 0) * 32 + lane) * 4];
            uint4 b1v = *(const uint4*)&WhS[((((ws * 16 + ksl) * 2 + wq) * 2 + 1) * 32 + lane) * 4];
            uint32_t A0[4] = {a0v.x, a0v.y, a0v.z, a0v.w};
            uint32_t A1[4] = {a1v.x, a1v.y, a1v.z, a1v.w};
            mma8(acc[0][0], A0, b0v.x, b0v.y);
            mma8(acc[0][1], A0, b0v.z, b0v.w);
            mma8(acc[0][2], A0, b1v.x, b1v.y);
            mma8(acc[0][3], A0, b1v.z, b1v.w);
            mma8(acc[1][0], A1, b0v.x, b0v.y);
            mma8(acc[1][1], A1, b0v.z, b0v.w);
            mma8(acc[1][2], A1, b1v.x, b1v.y);
            mma8(acc[1][3], A1, b1v.z, b1v.w);
        }
        __syncthreads();   // As dead; reuse as reduction scratch

        // --- k-split reduction: ws 1..3 write partials, ws 0 accumulates ---
        if (ws != 0) {
            #pragma unroll
            for (int mf = 0; mf < 2; mf++)
                #pragma unroll
                for (int nf = 0; nf < 4; nf++) {
                    int grp = mf * 4 + nf;
                    *(float4*)&redbuf[(((wq * 3 + (ws - 1)) * 8 + grp) * 32 + lane) * 4]
                        = *(float4*)acc[mf][nf];
                }
        }
        __syncthreads();
        if (ws == 0) {
            #pragma unroll
            for (int s = 0; s < 3; s++)
                #pragma unroll
                for (int mf = 0; mf < 2; mf++)
                    #pragma unroll
                    for (int nf = 0; nf < 4; nf++) {
                        int grp = mf * 4 + nf;
                        float4 r = *(const float4*)&redbuf[(((wq * 3 + s) * 8 + grp) * 32 + lane) * 4];
                        acc[mf][nf][0] += r.x; acc[mf][nf][1] += r.y;
                        acc[mf][nf][2] += r.z; acc[mf][nf][3] += r.w;
                    }
            // write final gates
            #pragma unroll
            for (int mf = 0; mf < 2; mf++)
                #pragma unroll
                for (int nf = 0; nf < 4; nf++) {
                    int row = mf * 16 + gid;
                    int col = wq * 32 + nf * 8 + tig * 2;
                    *(float2*)&gatebuf[row * 68 + col]       = make_float2(acc[mf][nf][0], acc[mf][nf][1]);
                    *(float2*)&gatebuf[(row + 8) * 68 + col] = make_float2(acc[mf][nf][2], acc[mf][nf][3]);
                }
        }
        __syncthreads();

        // --- fused LSTM epilogue (all threads; 2 cells each) ---
        {
            float4 gA = *(const float4*)&gatebuf[b_loc * 68 + hloc0 * 4];
            float4 gB = *(const float4*)&gatebuf[b_loc * 68 + hloc0 * 4 + 4];
            float f0 = sigf(gA.x + pA.x), i0 = sigf(gA.y + pA.y);
            float gg0 = tanhf(gA.z + pA.z), o0 = sigf(gA.w + pA.w);
            float f1 = sigf(gB.x + pB.x), i1 = sigf(gB.y + pB.y);
            float gg1 = tanhf(gB.z + pB.z), o1 = sigf(gB.w + pB.w);
            c0 = f0 * c0 + i0 * gg0;
            c1 = f1 * c1 + i1 * gg1;
            float h0 = o0 * tanhf(c0);
            float h1 = o1 * tanhf(c1);

            *(float2*)&out[(size_t)t * (BATCH * HID) + (size_t)bglob * HID + hg] = make_float2(h0, h1);
            g_hF[wb][hoff]     = h0;
            g_hF[wb][hoff + 4] = h1;

            if (t == T_STEPS - 1) {
                size_t tail = (size_t)T_STEPS * (BATCH * HID);
                *(float2*)&out[tail + (size_t)bglob * HID + hg]               = make_float2(h0, h1);
                *(float2*)&out[tail + (size_t)(BATCH * HID) + (size_t)bglob * HID + hg] = make_float2(c0, c1);
            }
        }

        // --- per-batch-group barrier (32 blocks) ---
        __syncthreads();
        if (tid == 0) {
            __threadfence();
            atomicAdd(&g_bar[bg], 1u);
            const unsigned int tgt = 32u * (unsigned)(t + 1);
            while (((volatile unsigned int*)g_bar)[bg] < tgt) { __nanosleep(32); }
            __threadfence();
        }
        __syncthreads();
    }
}

// ---------------- launch ----------------
extern "C" void kernel_launch(void* const* d_in, const int* in_sizes, int n_in,
                              void* d_out, int out_size) {
    const float* X  = (const float*)d_in[0];
    const float* Wf = (const float*)d_in[1];
    const float* bf = (const float*)d_in[2];
    const float* Wi = (const float*)d_in[3];
    const float* bi = (const float*)d_in[4];
    const float* Wg = (const float*)d_in[5];
    const float* bg = (const float*)d_in[6];
    const float* Wo = (const float*)d_in[7];
    const float* bo = (const float*)d_in[8];
    float* out = (float*)d_out;

    static int smem_set = 0;
    if (!smem_set) {
        cudaFuncSetAttribute(lstm_persist, cudaFuncAttributeMaxDynamicSharedMemorySize, 196608);
        smem_set = 1;
    }

    pack_wx<<<GCOLS, 512>>>(Wf, bf, Wi, bi, Wg, bg, Wo, bo);
    pack_whf<<<4096, 256>>>(Wf, Wi, Wg, Wo);
    init_state<<<512, 256>>>();
    gemm_pre<<<dim3(65536 / 64, GCOLS / 64), 256>>>(X);
    lstm_persist<<<128, 256, 196608>>>(out);
}

// round 4
// speedup vs baseline: 2.2552x; 1.1584x over previous
#include <cuda_runtime.h>
#include <cstdint>

#define T_STEPS 512
#define BATCH   128
#define HID     512
#define GCOLS   2048   // 4*HID, interleaved: j = 4*h + gate (0=f,1=i,2=g,3=o)
#define KDIM    512

// ---------------- static device scratch ----------------
__device__ __align__(256) float g_Wx[KDIM * GCOLS];                       // [k][j] tf32 (for pre-GEMM)
__device__ __align__(256) float g_WhF[HID * GCOLS];                       // frag-packed Wh (4MB)
__device__ __align__(256) float g_bias[GCOLS];
__device__ __align__(256) float g_pre[(size_t)T_STEPS * BATCH * GCOLS];   // x-proj + bias (512MB)
__device__ __align__(256) float g_hF[2][BATCH * HID];                     // h, fragment layout, dbl-buffered
__device__ unsigned int g_bar[4];                                         // per-batch-group barrier

// ---------------- helpers ----------------
__device__ __forceinline__ uint32_t f2tf(float f) {
    uint32_t u; asm("cvt.rna.tf32.f32 %0, %1;" : "=r"(u) : "f"(f)); return u;
}
__device__ __forceinline__ void cp16(void* s, const void* g) {
    uint32_t sa = (uint32_t)__cvta_generic_to_shared(s);
    asm volatile("cp.async.cg.shared.global [%0], [%1], 16;" :: "r"(sa), "l"(g));
}
__device__ __forceinline__ void cp_commit() { asm volatile("cp.async.commit_group;"); }
__device__ __forceinline__ void cp_wait0()  { asm volatile("cp.async.wait_group 0;"); }
__device__ __forceinline__ void cp_wait1()  { asm volatile("cp.async.wait_group 1;"); }

__device__ __forceinline__ void mma8(float* d, const uint32_t* a, uint32_t b0, uint32_t b1) {
    asm volatile(
        "mma.sync.aligned.m16n8k8.row.col.f32.tf32.tf32.f32 "
        "{%0,%1,%2,%3}, {%4,%5,%6,%7}, {%8,%9}, {%0,%1,%2,%3};"
        : "+f"(d[0]), "+f"(d[1]), "+f"(d[2]), "+f"(d[3])
        : "r"(a[0]), "r"(a[1]), "r"(a[2]), "r"(a[3]), "r"(b0), "r"(b1));
}

// fast accurate activations (no div.rn): ~2 ulp
__device__ __forceinline__ float sigf(float x) {
    return __fdividef(1.0f, 1.0f + __expf(-x));
}
__device__ __forceinline__ float tanhfast(float x) {
    float e = __expf(2.0f * x);
    return 1.0f - __fdividef(2.0f, e + 1.0f);
}

// release/acquire global barrier primitives
__device__ __forceinline__ void bar_arrive(unsigned int* p) {
    asm volatile("red.release.gpu.add.u32 [%0], %1;" :: "l"(p), "r"(1u) : "memory");
}
__device__ __forceinline__ unsigned int ld_acq(unsigned int* p) {
    unsigned int v;
    asm volatile("ld.acquire.gpu.u32 %0, [%1];" : "=r"(v) : "l"(p) : "memory");
    return v;
}

// ---------------- pack: Wx (k-major, for pre-GEMM) + bias ----------------
__global__ void pack_wx(const float* __restrict__ Wf, const float* __restrict__ bf,
                        const float* __restrict__ Wi, const float* __restrict__ bi,
                        const float* __restrict__ Wg, const float* __restrict__ bg,
                        const float* __restrict__ Wo, const float* __restrict__ bo) {
    int j = blockIdx.x;            // 0..2047
    int h = j >> 2, gi = j & 3;
    const float* W; const float* bb;
    if (gi == 0)      { W = Wf; bb = bf; }
    else if (gi == 1) { W = Wi; bb = bi; }
    else if (gi == 2) { W = Wg; bb = bg; }
    else              { W = Wo; bb = bo; }
    int k = threadIdx.x;           // 0..511
    g_Wx[k * GCOLS + j] = __uint_as_float(f2tf(W[h * 1024 + k]));
    if (k == 0) g_bias[j] = bb[h];
}

// ---------------- pack: Wh fragment layout ----------------
// g_WhF flat index: ((((nb*4 + ws)*16 + ksl)*2 + wq)*2 + pair)*32*4 + lane*4 + slot
__global__ void pack_whf(const float* __restrict__ Wf, const float* __restrict__ Wi,
                         const float* __restrict__ Wg, const float* __restrict__ Wo) {
    unsigned f = blockIdx.x * 256u + threadIdx.x;   // 0 .. 2^20-1
    int slot = f & 3;
    int lane = (f >> 2) & 31;
    int pair = (f >> 7) & 1;
    int wq   = (f >> 8) & 1;
    int ksl  = (f >> 9) & 15;
    int ws   = (f >> 13) & 3;
    int nb   = f >> 15;
    int gid = lane >> 2, tig = lane & 3;
    int nf  = pair * 2 + (slot >> 1);
    int b01 = slot & 1;
    int k   = ws * 128 + ksl * 8 + b01 * 4 + tig;
    int col = nb * 64 + wq * 32 + nf * 8 + gid;
    int h = col >> 2, gate = col & 3;
    const float* W;
    if (gate == 0) W = Wf; else if (gate == 1) W = Wi;
    else if (gate == 2) W = Wg; else W = Wo;
    g_WhF[f] = __uint_as_float(f2tf(W[h * 1024 + 512 + k]));
}

__global__ void init_state() {
    int i = blockIdx.x * blockDim.x + threadIdx.x;
    if (i < 4) g_bar[i] = 0;
    if (i < 2 * BATCH * HID) ((float*)g_hF)[i] = 0.0f;
}

// ---------------- precompute GEMM: pre = X @ WxT + bias ----------------
// BM=64 BN=128 BK=32, 256 threads, warps 2(M) x 4(N), warp tile 32x32.
// Grid (16 n-tiles fastest, 1024 m-tiles) so co-resident blocks share A via L2.
#define GP_ASZ (64 * 36)
#define GP_BSZ (32 * 132)
#define GP_SMEM ((2 * GP_ASZ + 2 * GP_BSZ) * 4)
__global__ __launch_bounds__(256) void gemm_pre(const float* __restrict__ X) {
    extern __shared__ float gsm[];
    float* Asb = gsm;                  // 2 x 64x36
    float* Bsb = gsm + 2 * GP_ASZ;     // 2 x 32x132
    const int tid = threadIdx.x;
    const int n0 = blockIdx.x * 128, m0 = blockIdx.y * 64;
    const int warp = tid >> 5, lane = tid & 31;
    const int wm = warp >> 2, wn = warp & 3;   // wm 0..1, wn 0..3
    const int gid = lane >> 2, tig = lane & 3;

    float acc[2][4][4];
    #pragma unroll
    for (int i0 = 0; i0 < 2; i0++)
        #pragma unroll
        for (int i1 = 0; i1 < 4; i1++)
            #pragma unroll
            for (int i2 = 0; i2 < 4; i2++) acc[i0][i1][i2] = 0.0f;

    auto load_tiles = [&](int buf, int k0) {
        float* A_ = Asb + buf * GP_ASZ;
        float* B_ = Bsb + buf * GP_BSZ;
        #pragma unroll
        for (int i = 0; i < 2; i++) {              // A: 512 float4 chunks (64 rows x 8)
            int c = tid * 2 + i;
            int row = c >> 3, cw = c & 7;
            cp16(&A_[row * 36 + cw * 4], X + (size_t)(m0 + row) * 512 + k0 + cw * 4);
        }
        #pragma unroll
        for (int i = 0; i < 4; i++) {              // B: 1024 float4 chunks (32 rows x 32)
            int c = tid * 4 + i;
            int row = c >> 5, cw = c & 31;
            cp16(&B_[row * 132 + cw * 4], g_Wx + (size_t)(k0 + row) * GCOLS + n0 + cw * 4);
        }
        cp_commit();
    };

    load_tiles(0, 0);
    for (int kt = 0; kt < 16; kt++) {
        if (kt < 15) { load_tiles((kt + 1) & 1, (kt + 1) * 32); cp_wait1(); }
        else cp_wait0();
        __syncthreads();
        const float* A_ = Asb + (kt & 1) * GP_ASZ;
        const float* B_ = Bsb + (kt & 1) * GP_BSZ;
        #pragma unroll
        for (int ks = 0; ks < 4; ks++) {
            const int kb = ks * 8;
            const int r = wm * 32;
            uint32_t a0[4], a1[4];
            a0[0] = __float_as_uint(A_[(r + gid) * 36 + kb + tig]);
            a0[1] = __float_as_uint(A_[(r + gid + 8) * 36 + kb + tig]);
            a0[2] = __float_as_uint(A_[(r + gid) * 36 + kb + tig + 4]);
            a0[3] = __float_as_uint(A_[(r + gid + 8) * 36 + kb + tig + 4]);
            a1[0] = __float_as_uint(A_[(r + 16 + gid) * 36 + kb + tig]);
            a1[1] = __float_as_uint(A_[(r + 24 + gid) * 36 + kb + tig]);
            a1[2] = __float_as_uint(A_[(r + 16 + gid) * 36 + kb + tig + 4]);
            a1[3] = __float_as_uint(A_[(r + 24 + gid) * 36 + kb + tig + 4]);
            #pragma unroll
            for (int nf = 0; nf < 4; nf++) {
                int cc = wn * 32 + nf * 8 + gid;
                uint32_t b0 = __float_as_uint(B_[(kb + tig) * 132 + cc]);
                uint32_t b1 = __float_as_uint(B_[(kb + tig + 4) * 132 + cc]);
                mma8(acc[0][nf], a0, b0, b1);
                mma8(acc[1][nf], a1, b0, b1);
            }
        }
        __syncthreads();
    }

    #pragma unroll
    for (int mf = 0; mf < 2; mf++)
        #pragma unroll
        for (int nf = 0; nf < 4; nf++) {
            int row0 = m0 + wm * 32 + mf * 16 + gid;
            int col  = n0 + wn * 32 + nf * 8 + tig * 2;
            float bb0 = g_bias[col], bb1 = g_bias[col + 1];
            float2 s0 = make_float2(acc[mf][nf][0] + bb0, acc[mf][nf][1] + bb1);
            float2 s1 = make_float2(acc[mf][nf][2] + bb0, acc[mf][nf][3] + bb1);
            *(float2*)&g_pre[(size_t)row0 * GCOLS + col]       = s0;
            *(float2*)&g_pre[(size_t)(row0 + 8) * GCOLS + col] = s1;
        }
}

// ---------------- persistent recurrent kernel ----------------
// Grid: 128 blocks = 4 batch-groups x 32 n-slices. 256 threads (8 warps).
// Block tile: 32 batch rows x 64 gate cols, K=512 split 4-way (S=4), 2 warps per n-half.
__global__ __launch_bounds__(256) void lstm_persist(float* __restrict__ out) {
    extern __shared__ float smem[];
    float* WhS = smem;               // 32768 floats (128KB)
    float* As  = smem + 32768;       // 16384 floats (h stage, frag layout)
    float* redbuf  = As;             // 6144 floats [wq][src3][grp8][lane][4]
    float* gatebuf = As + 6144;      // 32*68 floats

    const int tid  = threadIdx.x;
    const int lane = tid & 31;
    const int w    = tid >> 5;
    const int ws   = w >> 1;         // k-slice 0..3
    const int wq   = w & 1;          // n-half 0..1
    const int gid  = lane >> 2, tig = lane & 3;

    const int bg  = blockIdx.x >> 5;       // batch group 0..3
    const int nb  = blockIdx.x & 31;       // n-slice 0..31
    const int b0_ = bg * 32;
    const int n0  = nb * 64;
    const int mg0 = bg * 2;

    // --- load full Wh slice into smem: 32768 floats = 32 iters x 256 thr x 16B ---
    {
        const float* src = g_WhF + (size_t)nb * 32768;
        #pragma unroll
        for (int i = 0; i < 32; i++) {
            int c = tid + i * 256;
            cp16(&WhS[c * 4], src + (size_t)c * 4);
        }
        cp_commit(); cp_wait0();
        __syncthreads();
    }

    // epilogue cell mapping (fixed for all steps)
    const int b_loc = tid >> 3;            // 0..31
    const int hloc0 = (tid & 7) * 2;       // 0..14
    const int bglob = b0_ + b_loc;
    const int hg    = nb * 16 + hloc0;     // global h index of cell0
    // h fragment-layout offset for (bglob, k=hg)
    const int mg_e = bglob >> 4, rr = bglob & 15, up = rr >> 3, gb = rr & 7;
    const int wsk = hg >> 7, kslk = (hg >> 3) & 15, tigk = hg & 3, hik = (hg >> 2) & 1;
    const int hoff = (((mg_e * 4 + wsk) * 16 + kslk) * 32 + (gb * 4 + tigk)) * 4 + (up + 2 * hik);

    float c0 = 0.0f, c1 = 0.0f;

    // prefetch pre[0]
    const float* prbase = g_pre + (size_t)bglob * GCOLS + n0 + hloc0 * 4;
    float4 pA = *(const float4*)prbase;
    float4 pB = *(const float4*)(prbase + 4);

    for (int t = 0; t < T_STEPS; t++) {
        const int rb = t & 1, wb = rb ^ 1;

        // --- stage h[rb] (64KB contiguous, frag layout) ---
        const float* src = g_hF[rb] + mg0 * 8192;
        #pragma unroll
        for (int i = 0; i < 16; i++) {
            int c = tid + i * 256;
            cp16(&As[c * 4], src + c * 4);
        }
        cp_commit();
        cp_wait0();
        __syncthreads();

        // --- mainloop: warp (ws,wq) computes 32x32 over k in [ws*128, ws*128+128) ---
        float acc[2][4][4];
        #pragma unroll
        for (int i0 = 0; i0 < 2; i0++)
            #pragma unroll
            for (int i1 = 0; i1 < 4; i1++)
                #pragma unroll
                for (int i2 = 0; i2 < 4; i2++) acc[i0][i1][i2] = 0.0f;

        #pragma unroll
        for (int ksl = 0; ksl < 16; ksl++) {
            uint4 a0v = *(const uint4*)&As[(((0 * 4 + ws) * 16 + ksl) * 32 + lane) * 4];
            uint4 a1v = *(const uint4*)&As[(((1 * 4 + ws) * 16 + ksl) * 32 + lane) * 4];
            uint4 b0v = *(const uint4*)&WhS[((((ws * 16 + ksl) * 2 + wq) * 2 + 0) * 32 + lane) * 4];
            uint4 b1v = *(const uint4*)&WhS[((((ws * 16 + ksl) * 2 + wq) * 2 + 1) * 32 + lane) * 4];
            uint32_t A0[4] = {a0v.x, a0v.y, a0v.z, a0v.w};
            uint32_t A1[4] = {a1v.x, a1v.y, a1v.z, a1v.w};
            mma8(acc[0][0], A0, b0v.x, b0v.y);
            mma8(acc[0][1], A0, b0v.z, b0v.w);
            mma8(acc[0][2], A0, b1v.x, b1v.y);
            mma8(acc[0][3], A0, b1v.z, b1v.w);
            mma8(acc[1][0], A1, b0v.x, b0v.y);
            mma8(acc[1][1], A1, b0v.z, b0v.w);
            mma8(acc[1][2], A1, b1v.x, b1v.y);
            mma8(acc[1][3], A1, b1v.z, b1v.w);
        }
        __syncthreads();   // As dead; reuse as reduction scratch

        // --- k-split reduction: ws 1..3 write partials, ws 0 accumulates ---
        if (ws != 0) {
            #pragma unroll
            for (int mf = 0; mf < 2; mf++)
                #pragma unroll
                for (int nf = 0; nf < 4; nf++) {
                    int grp = mf * 4 + nf;
                    *(float4*)&redbuf[(((wq * 3 + (ws - 1)) * 8 + grp) * 32 + lane) * 4]
                        = *(float4*)acc[mf][nf];
                }
        }
        __syncthreads();
        if (ws == 0) {
            #pragma unroll
            for (int s = 0; s < 3; s++)
                #pragma unroll
                for (int mf = 0; mf < 2; mf++)
                    #pragma unroll
                    for (int nf = 0; nf < 4; nf++) {
                        int grp = mf * 4 + nf;
                        float4 r = *(const float4*)&redbuf[(((wq * 3 + s) * 8 + grp) * 32 + lane) * 4];
                        acc[mf][nf][0] += r.x; acc[mf][nf][1] += r.y;
                        acc[mf][nf][2] += r.z; acc[mf][nf][3] += r.w;
                    }
            // write final gates
            #pragma unroll
            for (int mf = 0; mf < 2; mf++)
                #pragma unroll
                for (int nf = 0; nf < 4; nf++) {
                    int row = mf * 16 + gid;
                    int col = wq * 32 + nf * 8 + tig * 2;
                    *(float2*)&gatebuf[row * 68 + col]       = make_float2(acc[mf][nf][0], acc[mf][nf][1]);
                    *(float2*)&gatebuf[(row + 8) * 68 + col] = make_float2(acc[mf][nf][2], acc[mf][nf][3]);
                }
        }
        __syncthreads();

        // --- fused LSTM epilogue (all threads; 2 cells each) ---
        float h0, h1;
        {
            float4 gA = *(const float4*)&gatebuf[b_loc * 68 + hloc0 * 4];
            float4 gB = *(const float4*)&gatebuf[b_loc * 68 + hloc0 * 4 + 4];
            float f0 = sigf(gA.x + pA.x), i0 = sigf(gA.y + pA.y);
            float gg0 = tanhfast(gA.z + pA.z), o0 = sigf(gA.w + pA.w);
            float f1 = sigf(gB.x + pB.x), i1 = sigf(gB.y + pB.y);
            float gg1 = tanhfast(gB.z + pB.z), o1 = sigf(gB.w + pB.w);
            c0 = f0 * c0 + i0 * gg0;
            c1 = f1 * c1 + i1 * gg1;
            h0 = o0 * tanhfast(c0);
            h1 = o1 * tanhfast(c1);
            // h for next step (consumed by other blocks)
            g_hF[wb][hoff]     = h0;
            g_hF[wb][hoff + 4] = h1;
        }

        // --- arrive, then do non-critical work in the barrier shadow ---
        __syncthreads();
        if (tid == 0) bar_arrive(&g_bar[bg]);

        // out store (not consumed by anyone this run)
        *(float2*)&out[(size_t)t * (BATCH * HID) + (size_t)bglob * HID + hg] = make_float2(h0, h1);
        if (t == T_STEPS - 1) {
            size_t tail = (size_t)T_STEPS * (BATCH * HID);
            *(float2*)&out[tail + (size_t)bglob * HID + hg]                         = make_float2(h0, h1);
            *(float2*)&out[tail + (size_t)(BATCH * HID) + (size_t)bglob * HID + hg] = make_float2(c0, c1);
        }
        // prefetch pre[t+1] from DRAM while waiting
        {
            int tn = (t + 1 < T_STEPS) ? t + 1 : t;
            const float* prp = prbase + (size_t)tn * (BATCH * GCOLS);
            pA = *(const float4*)prp;
            pB = *(const float4*)(prp + 4);
        }

        if (tid == 0) {
            const unsigned int tgt = 32u * (unsigned)(t + 1);
            while (ld_acq(&g_bar[bg]) < tgt) { }
        }
        __syncthreads();
    }
}

// ---------------- launch ----------------
extern "C" void kernel_launch(void* const* d_in, const int* in_sizes, int n_in,
                              void* d_out, int out_size) {
    const float* X  = (const float*)d_in[0];
    const float* Wf = (const float*)d_in[1];
    const float* bf = (const float*)d_in[2];
    const float* Wi = (const float*)d_in[3];
    const float* bi = (const float*)d_in[4];
    const float* Wg = (const float*)d_in[5];
    const float* bg = (const float*)d_in[6];
    const float* Wo = (const float*)d_in[7];
    const float* bo = (const float*)d_in[8];
    float* out = (float*)d_out;

    static int smem_set = 0;
    if (!smem_set) {
        cudaFuncSetAttribute(lstm_persist, cudaFuncAttributeMaxDynamicSharedMemorySize, 196608);
        cudaFuncSetAttribute(gemm_pre, cudaFuncAttributeMaxDynamicSharedMemorySize, GP_SMEM);
        smem_set = 1;
    }

    pack_wx<<<GCOLS, 512>>>(Wf, bf, Wi, bi, Wg, bg, Wo, bo);
    pack_whf<<<4096, 256>>>(Wf, Wi, Wg, Wo);
    init_state<<<512, 256>>>();
    gemm_pre<<<dim3(GCOLS / 128, 65536 / 64), 256, GP_SMEM>>>(X);
    lstm_persist<<<128, 256, 196608>>>(out);
}

// round 5
// speedup vs baseline: 3.7070x; 1.6438x over previous
#include <cuda_runtime.h>
#include <cuda_fp16.h>
#include <cstdint>

#define T_STEPS 512
#define BATCH   128
#define HID     512
#define GCOLS   2048   // 4*HID, interleaved: j = 4*h + gate (0=f,1=i,2=g,3=o)
#define KDIM    512

// ---------------- static device scratch ----------------
// fp16 fragment-packed layouts (m16n8k16). Chunk = 32 lanes x 4 uint32 = 512B.
// A-side chunk (mgrp, ksl): reg0 = {A[g][2t],A[g][2t+1]}, reg1 = row g+8, reg2 = k+8, reg3 = both.
// B-side chunk (n16, ksl): reg0 = b0 of n8-lo, reg1 = b1 n8-lo, reg2 = b0 n8-hi, reg3 = b1 n8-hi.
__device__ __align__(256) uint32_t g_Xh[4096u * 32 * 128];     // X fp16 frags (64MB) [mgrp][ksl][lane][4]
__device__ __align__(256) uint32_t g_Wxh[128 * 32 * 128];      // Wx fp16 frags [n16][ksl][lane][4]
__device__ __align__(256) uint32_t g_Whh[128 * 32 * 128];      // Wh fp16 frags [n16][ksl][lane][4]
__device__ __align__(256) float    g_bias[GCOLS];
__device__ __align__(256) float    g_pre[(size_t)T_STEPS * BATCH * GCOLS];  // x-proj + bias (fp32)
__device__ __align__(256) uint32_t g_hFh[2][8 * 32 * 128];     // h fp16 frags [mg][ksl][lane][4], dbl-buf
__device__ unsigned int g_bar[4];

// ---------------- helpers ----------------
__device__ __forceinline__ void cp16(void* s, const void* g) {
    uint32_t sa = (uint32_t)__cvta_generic_to_shared(s);
    asm volatile("cp.async.cg.shared.global [%0], [%1], 16;" :: "r"(sa), "l"(g));
}
__device__ __forceinline__ void cp_commit() { asm volatile("cp.async.commit_group;"); }
__device__ __forceinline__ void cp_wait0()  { asm volatile("cp.async.wait_group 0;"); }
__device__ __forceinline__ void cp_wait1()  { asm volatile("cp.async.wait_group 1;"); }

__device__ __forceinline__ void mma16(float* d, const uint32_t* a, uint32_t b0, uint32_t b1) {
    asm volatile(
        "mma.sync.aligned.m16n8k16.row.col.f32.f16.f16.f32 "
        "{%0,%1,%2,%3}, {%4,%5,%6,%7}, {%8,%9}, {%0,%1,%2,%3};"
        : "+f"(d[0]), "+f"(d[1]), "+f"(d[2]), "+f"(d[3])
        : "r"(a[0]), "r"(a[1]), "r"(a[2]), "r"(a[3]), "r"(b0), "r"(b1));
}

__device__ __forceinline__ float sigf(float x) {
    return __fdividef(1.0f, 1.0f + __expf(-x));
}
__device__ __forceinline__ float tanhfast(float x) {
    float e = __expf(2.0f * x);
    return 1.0f - __fdividef(2.0f, e + 1.0f);
}
__device__ __forceinline__ uint32_t packh2(float lo, float hi) {
    return ((uint32_t)__half_as_ushort(__float2half_rn(hi)) << 16)
         | (uint32_t)__half_as_ushort(__float2half_rn(lo));
}

__device__ __forceinline__ void bar_arrive(unsigned int* p) {
    asm volatile("red.release.gpu.add.u32 [%0], %1;" :: "l"(p), "r"(1u) : "memory");
}
__device__ __forceinline__ unsigned int ld_acq(unsigned int* p) {
    unsigned int v;
    asm volatile("ld.acquire.gpu.u32 %0, [%1];" : "=r"(v) : "l"(p) : "memory");
    return v;
}

// ---------------- pack: Wx + Wh fp16 frags + bias ----------------
__global__ void pack_w(const float* __restrict__ Wf, const float* __restrict__ bf,
                       const float* __restrict__ Wi, const float* __restrict__ bi,
                       const float* __restrict__ Wg, const float* __restrict__ bg_,
                       const float* __restrict__ Wo, const float* __restrict__ bo) {
    unsigned idx = blockIdx.x * 256u + threadIdx.x;  // 0..524287
    int reg = idx & 3, lane = (idx >> 2) & 31, ksl = (idx >> 7) & 31, n16 = idx >> 12;
    int g = lane >> 2, t = lane & 3;
    int n = n16 * 16 + (reg >> 1) * 8 + g;         // B-frag: reg>>1 selects n8 half
    int kb = ksl * 16 + (reg & 1) * 8 + 2 * t;     // reg&1 selects k half (b0/b1)
    int h = n >> 2, gate = n & 3;
    const float* W = (gate == 0) ? Wf : (gate == 1) ? Wi : (gate == 2) ? Wg : Wo;
    g_Wxh[idx] = packh2(W[h * 1024 + kb],       W[h * 1024 + kb + 1]);
    g_Whh[idx] = packh2(W[h * 1024 + 512 + kb], W[h * 1024 + 512 + kb + 1]);
    if (idx < GCOLS) {
        int j = idx, h2 = j >> 2, g2 = j & 3;
        const float* bb = (g2 == 0) ? bf : (g2 == 1) ? bi : (g2 == 2) ? bg_ : bo;
        g_bias[j] = bb[h2];
    }
}

// ---------------- pack: X fp16 frags ----------------
__global__ void pack_x(const float* __restrict__ X) {
    unsigned idx = blockIdx.x * 256u + threadIdx.x;  // 0..16777215
    int reg = idx & 3, lane = (idx >> 2) & 31, ksl = (idx >> 7) & 31;
    unsigned mgrp = idx >> 12;
    int g = lane >> 2, t = lane & 3;
    unsigned m = mgrp * 16 + (reg & 1) * 8 + g;    // A-frag: reg&1 selects row half
    int kb = ksl * 16 + (reg >> 1) * 8 + 2 * t;    // reg>>1 selects k half
    const float* p = X + (size_t)m * 512 + kb;
    g_Xh[idx] = packh2(p[0], p[1]);
}

__global__ void init_state() {
    unsigned i = blockIdx.x * 256u + threadIdx.x;
    if (i < 4) g_bar[i] = 0;
    if (i < 2u * 8 * 32 * 128) ((uint32_t*)g_hFh)[i] = 0u;
}

// ---------------- precompute GEMM: pre = X @ WxT + bias (fp16 frags, fp32 accum) ----------------
// BM=64 BN=128 BK=32, 256 threads, warps 2(M) x 4(N), warp tile 32x32. n-fastest grid.
__global__ __launch_bounds__(256) void gemm_pre() {
    __shared__ __align__(128) uint32_t Asm[2][8 * 128];    // 4 mgrp x 2 ksl chunks
    __shared__ __align__(128) uint32_t Bsm[2][16 * 128];   // 8 n16  x 2 ksl chunks
    const int tid = threadIdx.x;
    const int n16_0 = blockIdx.x * 8;        // n0 = blockIdx.x*128
    const int mgrp0 = blockIdx.y * 4;        // m0 = blockIdx.y*64
    const int n0 = n16_0 * 16, m0 = mgrp0 * 16;
    const int warp = tid >> 5, lane = tid & 31;
    const int wm = warp >> 2, wn = warp & 3;
    const int gid = lane >> 2, tig = lane & 3;

    float acc[2][4][4];
    #pragma unroll
    for (int i0 = 0; i0 < 2; i0++)
        #pragma unroll
        for (int i1 = 0; i1 < 4; i1++)
            #pragma unroll
            for (int i2 = 0; i2 < 4; i2++) acc[i0][i1][i2] = 0.0f;

    auto load_tiles = [&](int buf, int kt) {
        {   // A: 8 chunks, 1 slot per thread
            int chunk = tid >> 5, ln = tid & 31;
            unsigned gc = (mgrp0 + (chunk >> 1)) * 32u + 2 * kt + (chunk & 1);
            cp16(&Asm[buf][chunk * 128 + ln * 4], g_Xh + (size_t)gc * 128 + ln * 4);
        }
        #pragma unroll
        for (int i = 0; i < 2; i++) {   // B: 16 chunks, 2 slots per thread
            int slot = tid * 2 + i;
            int chunk = slot >> 5, ln = slot & 31;
            unsigned gc = (n16_0 + (chunk >> 1)) * 32u + 2 * kt + (chunk & 1);
            cp16(&Bsm[buf][chunk * 128 + ln * 4], g_Wxh + (size_t)gc * 128 + ln * 4);
        }
        cp_commit();
    };

    load_tiles(0, 0);
    for (int kt = 0; kt < 16; kt++) {
        if (kt < 15) { load_tiles((kt + 1) & 1, kt + 1); cp_wait1(); }
        else cp_wait0();
        __syncthreads();
        const uint32_t* A_ = Asm[kt & 1];
        const uint32_t* B_ = Bsm[kt & 1];
        #pragma unroll
        for (int ksll = 0; ksll < 2; ksll++) {
            uint4 av0 = *(const uint4*)&A_[((wm * 2 + 0) * 2 + ksll) * 128 + lane * 4];
            uint4 av1 = *(const uint4*)&A_[((wm * 2 + 1) * 2 + ksll) * 128 + lane * 4];
            uint32_t A0[4] = {av0.x, av0.y, av0.z, av0.w};
            uint32_t A1[4] = {av1.x, av1.y, av1.z, av1.w};
            #pragma unroll
            for (int cl = 0; cl < 2; cl++) {
                uint4 bv = *(const uint4*)&B_[((wn * 2 + cl) * 2 + ksll) * 128 + lane * 4];
                mma16(acc[0][cl * 2 + 0], A0, bv.x, bv.y);
                mma16(acc[0][cl * 2 + 1], A0, bv.z, bv.w);
                mma16(acc[1][cl * 2 + 0], A1, bv.x, bv.y);
                mma16(acc[1][cl * 2 + 1], A1, bv.z, bv.w);
            }
        }
        __syncthreads();
    }

    #pragma unroll
    for (int mf = 0; mf < 2; mf++)
        #pragma unroll
        for (int nf = 0; nf < 4; nf++) {
            int row0 = m0 + wm * 32 + mf * 16 + gid;
            int col  = n0 + wn * 32 + nf * 8 + tig * 2;
            float bb0 = g_bias[col], bb1 = g_bias[col + 1];
            float2 s0 = make_float2(acc[mf][nf][0] + bb0, acc[mf][nf][1] + bb1);
            float2 s1 = make_float2(acc[mf][nf][2] + bb0, acc[mf][nf][3] + bb1);
            *(float2*)&g_pre[(size_t)row0 * GCOLS + col]       = s0;
            *(float2*)&g_pre[(size_t)(row0 + 8) * GCOLS + col] = s1;
        }
}

// ---------------- persistent recurrent kernel (fp16 operands) ----------------
// Grid: 128 blocks = 4 batch-groups x 32 n-slices. 256 threads (8 warps = S4 x Q2).
__global__ __launch_bounds__(256) void lstm_persist(float* __restrict__ out) {
    extern __shared__ uint32_t sm32[];
    uint32_t* WhS = sm32;                    // 16384 u32 (64KB): [n16l(4)][ksl(32)][lane][4]
    uint32_t* As  = sm32 + 16384;            // 8192 u32 (32KB): [mgl(2)][ksl(32)][lane][4]
    float* redbuf  = (float*)As;             // reuse (6144 floats <= 8192 u32)
    float* gatebuf = (float*)(sm32 + 16384 + 8192);   // 2176 floats

    const int tid  = threadIdx.x;
    const int lane = tid & 31;
    const int w    = tid >> 5;
    const int ws   = w >> 1;         // k-slice 0..3 (k range 128)
    const int wq   = w & 1;          // n-half 0..1
    const int gid  = lane >> 2, tig = lane & 3;

    const int bg  = blockIdx.x >> 5;       // batch group 0..3
    const int nb  = blockIdx.x & 31;       // n-slice 0..31
    const int b0_ = bg * 32;
    const int n0  = nb * 64;

    // --- load Wh slice (64KB = 4096 cp16 / 256 thr = 16 each) ---
    {
        const uint32_t* src = g_Whh + (size_t)nb * 16384;
        #pragma unroll
        for (int i = 0; i < 16; i++) {
            int c = tid + i * 256;
            cp16(&WhS[c * 4], src + (size_t)c * 4);
        }
        cp_commit(); cp_wait0();
        __syncthreads();
    }

    // epilogue cell mapping (fixed): 2 cells (bglob, hg), (bglob, hg+1)
    const int b_loc = tid >> 3;            // 0..31
    const int hloc0 = (tid & 7) * 2;       // 0..14 even
    const int bglob = b0_ + b_loc;
    const int hg    = nb * 16 + hloc0;
    // h frag-layout offset: both cells share one uint32 (k pair)
    const int mg_h = bglob >> 4;
    const int rr   = bglob & 15;
    const int g_m  = rr & 7, hi_m = rr >> 3;
    const int ksl_h = hg >> 4;
    const int kk   = hg & 15;
    const int hi_k = kk >> 3, tig_k = (kk >> 1) & 3;
    const int hoff32 = ((mg_h * 32 + ksl_h) * 32 + (g_m * 4 + tig_k)) * 4 + (hi_m + 2 * hi_k);

    float c0 = 0.0f, c1 = 0.0f;

    // prefetch pre[0]
    const float* prbase = g_pre + (size_t)bglob * GCOLS + n0 + hloc0 * 4;
    float4 pA = *(const float4*)prbase;
    float4 pB = *(const float4*)(prbase + 4);

    for (int t = 0; t < T_STEPS; t++) {
        const int rb = t & 1, wb = rb ^ 1;

        // --- stage h[rb]: 32KB = 2048 cp16 / 256 thr = 8 each ---
        const uint32_t* src = g_hFh[rb] + bg * 8192;
        #pragma unroll
        for (int i = 0; i < 8; i++) {
            int c = tid + i * 256;
            cp16(&As[c * 4], src + c * 4);
        }
        cp_commit();
        cp_wait0();
        __syncthreads();

        // --- mainloop: warp (ws,wq): 32m x 32n, k in [ws*128, +128) ---
        float acc[2][4][4];
        #pragma unroll
        for (int i0 = 0; i0 < 2; i0++)
            #pragma unroll
            for (int i1 = 0; i1 < 4; i1++)
                #pragma unroll
                for (int i2 = 0; i2 < 4; i2++) acc[i0][i1][i2] = 0.0f;

        #pragma unroll
        for (int ksl = 0; ksl < 8; ksl++) {
            const int kg = ws * 8 + ksl;
            uint4 a0v = *(const uint4*)&As[(0 * 32 + kg) * 128 + lane * 4];
            uint4 a1v = *(const uint4*)&As[(1 * 32 + kg) * 128 + lane * 4];
            uint4 b0v = *(const uint4*)&WhS[((wq * 2 + 0) * 32 + kg) * 128 + lane * 4];
            uint4 b1v = *(const uint4*)&WhS[((wq * 2 + 1) * 32 + kg) * 128 + lane * 4];
            uint32_t A0[4] = {a0v.x, a0v.y, a0v.z, a0v.w};
            uint32_t A1[4] = {a1v.x, a1v.y, a1v.z, a1v.w};
            mma16(acc[0][0], A0, b0v.x, b0v.y);
            mma16(acc[0][1], A0, b0v.z, b0v.w);
            mma16(acc[0][2], A0, b1v.x, b1v.y);
            mma16(acc[0][3], A0, b1v.z, b1v.w);
            mma16(acc[1][0], A1, b0v.x, b0v.y);
            mma16(acc[1][1], A1, b0v.z, b0v.w);
            mma16(acc[1][2], A1, b1v.x, b1v.y);
            mma16(acc[1][3], A1, b1v.z, b1v.w);
        }
        __syncthreads();   // As dead; reuse as reduction scratch

        // --- k-split reduction ---
        if (ws != 0) {
            #pragma unroll
            for (int mf = 0; mf < 2; mf++)
                #pragma unroll
                for (int nf = 0; nf < 4; nf++) {
                    int grp = mf * 4 + nf;
                    *(float4*)&redbuf[(((wq * 3 + (ws - 1)) * 8 + grp) * 32 + lane) * 4]
                        = *(float4*)acc[mf][nf];
                }
        }
        __syncthreads();
        if (ws == 0) {
            #pragma unroll
            for (int s = 0; s < 3; s++)
                #pragma unroll
                for (int mf = 0; mf < 2; mf++)
                    #pragma unroll
                    for (int nf = 0; nf < 4; nf++) {
                        int grp = mf * 4 + nf;
                        float4 r = *(const float4*)&redbuf[(((wq * 3 + s) * 8 + grp) * 32 + lane) * 4];
                        acc[mf][nf][0] += r.x; acc[mf][nf][1] += r.y;
                        acc[mf][nf][2] += r.z; acc[mf][nf][3] += r.w;
                    }
            #pragma unroll
            for (int mf = 0; mf < 2; mf++)
                #pragma unroll
                for (int nf = 0; nf < 4; nf++) {
                    int row = mf * 16 + gid;
                    int col = wq * 32 + nf * 8 + tig * 2;
                    *(float2*)&gatebuf[row * 68 + col]       = make_float2(acc[mf][nf][0], acc[mf][nf][1]);
                    *(float2*)&gatebuf[(row + 8) * 68 + col] = make_float2(acc[mf][nf][2], acc[mf][nf][3]);
                }
        }
        __syncthreads();

        // --- fused LSTM epilogue (2 cells per thread) ---
        float h0, h1;
        {
            float4 gA = *(const float4*)&gatebuf[b_loc * 68 + hloc0 * 4];
            float4 gB = *(const float4*)&gatebuf[b_loc * 68 + hloc0 * 4 + 4];
            float f0 = sigf(gA.x + pA.x), i0 = sigf(gA.y + pA.y);
            float gg0 = tanhfast(gA.z + pA.z), o0 = sigf(gA.w + pA.w);
            float f1 = sigf(gB.x + pB.x), i1 = sigf(gB.y + pB.y);
            float gg1 = tanhfast(gB.z + pB.z), o1 = sigf(gB.w + pB.w);
            c0 = f0 * c0 + i0 * gg0;
            c1 = f1 * c1 + i1 * gg1;
            h0 = o0 * tanhfast(c0);
            h1 = o1 * tanhfast(c1);
            g_hFh[wb][hoff32] = packh2(h0, h1);   // fp16 h for next step
        }

        // --- arrive, then non-critical work in the barrier shadow ---
        __syncthreads();
        if (tid == 0) bar_arrive(&g_bar[bg]);

        *(float2*)&out[(size_t)t * (BATCH * HID) + (size_t)bglob * HID + hg] = make_float2(h0, h1);
        if (t == T_STEPS - 1) {
            size_t tail = (size_t)T_STEPS * (BATCH * HID);
            *(float2*)&out[tail + (size_t)bglob * HID + hg]                         = make_float2(h0, h1);
            *(float2*)&out[tail + (size_t)(BATCH * HID) + (size_t)bglob * HID + hg] = make_float2(c0, c1);
        }
        {   // prefetch pre[t+1] while waiting
            int tn = (t + 1 < T_STEPS) ? t + 1 : t;
            const float* prp = prbase + (size_t)tn * (BATCH * GCOLS);
            pA = *(const float4*)prp;
            pB = *(const float4*)(prp + 4);
        }

        if (tid == 0) {
            const unsigned int tgt = 32u * (unsigned)(t + 1);
            while (ld_acq(&g_bar[bg]) < tgt) { }
        }
        __syncthreads();
    }
}

// ---------------- launch ----------------
extern "C" void kernel_launch(void* const* d_in, const int* in_sizes, int n_in,
                              void* d_out, int out_size) {
    const float* X  = (const float*)d_in[0];
    const float* Wf = (const float*)d_in[1];
    const float* bf = (const float*)d_in[2];
    const float* Wi = (const float*)d_in[3];
    const float* bi = (const float*)d_in[4];
    const float* Wg = (const float*)d_in[5];
    const float* bg = (const float*)d_in[6];
    const float* Wo = (const float*)d_in[7];
    const float* bo = (const float*)d_in[8];
    float* out = (float*)d_out;

    static int smem_set = 0;
    if (!smem_set) {
        cudaFuncSetAttribute(lstm_persist, cudaFuncAttributeMaxDynamicSharedMemorySize, 107008);
        smem_set = 1;
    }

    pack_w<<<2048, 256>>>(Wf, bf, Wi, bi, Wg, bg, Wo, bo);
    pack_x<<<65536, 256>>>(X);
    init_state<<<256, 256>>>();
    gemm_pre<<<dim3(GCOLS / 128, 65536 / 64), 256>>>();
    lstm_persist<<<128, 256, 107008>>>(out);
}